// round 1
// baseline (speedup 1.0000x reference)
#include <cuda_runtime.h>
#include <mma.h>

using namespace nvcuda;

// Problem dims (fixed by reference)
#define BSZ  8
#define SDIM 2048
#define IDIM 1024
#define HDIM 4096
#define ODIM 1024
#define MDIM (BSZ * SDIM)   // 16384

// Scratch (no cudaMalloc allowed)
__device__ float g_decay[(size_t)MDIM * IDIM];     // 64 MB
__device__ float g_combined[(size_t)MDIM * IDIM];  // 64 MB
__device__ float g_hidden[(size_t)MDIM * HDIM];    // 256 MB

// ---------------------------------------------------------------------------
// TF32 GEMM: C[m,n] = sum_k A[m,k] * B[n,k]
// A row-major [M,K], B row-major [N,K]  (so B acts as col-major k x n for wmma)
// Tile: 128x64x16, 256 threads (8 warps: 4 along M x 2 along N, 32x32 each)
// ---------------------------------------------------------------------------
template <int BM, int BN, int BK>
__global__ void __launch_bounds__(256) gemm_tf32(const float* __restrict__ A,
                                                 const float* __restrict__ B,
                                                 float* __restrict__ C,
                                                 int M, int N, int K) {
    __shared__ float As[BM][BK];
    __shared__ float Bs[BN][BK];

    const int tid  = threadIdx.x;
    const int warp = tid >> 5;
    const int wm   = warp & 3;   // 0..3 (M direction)
    const int wn   = warp >> 2;  // 0..1 (N direction)
    const int bm   = blockIdx.y * BM;
    const int bn   = blockIdx.x * BN;

    wmma::fragment<wmma::accumulator, 16, 16, 8, float> c[2][2];
#pragma unroll
    for (int i = 0; i < 2; i++)
#pragma unroll
        for (int j = 0; j < 2; j++) wmma::fill_fragment(c[i][j], 0.0f);

    const int lr = tid >> 2;        // 0..63
    const int lc = (tid & 3) * 4;   // 0,4,8,12

    for (int k0 = 0; k0 < K; k0 += BK) {
        // A tile: 128 rows x 16 cols, each thread: 2 float4 (rows lr, lr+64)
        *(float4*)&As[lr][lc] =
            *(const float4*)&A[(size_t)(bm + lr) * K + k0 + lc];
        *(float4*)&As[lr + 64][lc] =
            *(const float4*)&A[(size_t)(bm + lr + 64) * K + k0 + lc];
        // B tile: 64 rows x 16 cols, each thread: 1 float4
        *(float4*)&Bs[lr][lc] =
            *(const float4*)&B[(size_t)(bn + lr) * K + k0 + lc];
        __syncthreads();

#pragma unroll
        for (int kk = 0; kk < BK; kk += 8) {
            wmma::fragment<wmma::matrix_a, 16, 16, 8, wmma::precision::tf32,
                           wmma::row_major> a[2];
            wmma::fragment<wmma::matrix_b, 16, 16, 8, wmma::precision::tf32,
                           wmma::col_major> b[2];
#pragma unroll
            for (int i = 0; i < 2; i++) {
                wmma::load_matrix_sync(a[i], &As[wm * 32 + i * 16][kk], BK);
#pragma unroll
                for (int e = 0; e < a[i].num_elements; e++)
                    a[i].x[e] = wmma::__float_to_tf32(a[i].x[e]);
            }
#pragma unroll
            for (int j = 0; j < 2; j++) {
                wmma::load_matrix_sync(b[j], &Bs[wn * 32 + j * 16][kk], BK);
#pragma unroll
                for (int e = 0; e < b[j].num_elements; e++)
                    b[j].x[e] = wmma::__float_to_tf32(b[j].x[e]);
            }
#pragma unroll
            for (int i = 0; i < 2; i++)
#pragma unroll
                for (int j = 0; j < 2; j++)
                    wmma::mma_sync(c[i][j], a[i], b[j], c[i][j]);
        }
        __syncthreads();
    }

#pragma unroll
    for (int i = 0; i < 2; i++)
#pragma unroll
        for (int j = 0; j < 2; j++) {
            float* dst =
                &C[(size_t)(bm + wm * 32 + i * 16) * N + bn + wn * 32 + j * 16];
            wmma::store_matrix_sync(dst, c[i][j], N, wmma::mem_row_major);
        }
}

// ---------------------------------------------------------------------------
// Elementwise epilogues (N is compile-time power of 2 -> idx % N is an AND)
// ---------------------------------------------------------------------------
template <int N>
__global__ void ep_sigmoid(float* __restrict__ y, const float* __restrict__ bias,
                           size_t total) {
    for (size_t idx = (size_t)blockIdx.x * blockDim.x + threadIdx.x; idx < total;
         idx += (size_t)gridDim.x * blockDim.x) {
        float v = y[idx] + bias[idx % N];
        y[idx] = 1.0f / (1.0f + __expf(-v));
    }
}

template <int N>
__global__ void ep_bias_relu(float* __restrict__ y,
                             const float* __restrict__ bias, size_t total) {
    for (size_t idx = (size_t)blockIdx.x * blockDim.x + threadIdx.x; idx < total;
         idx += (size_t)gridDim.x * blockDim.x) {
        float v = y[idx] + bias[idx % N];
        y[idx] = v > 0.0f ? v : 0.0f;
    }
}

template <int N>
__global__ void ep_bias(float* __restrict__ y, const float* __restrict__ bias,
                        size_t total) {
    for (size_t idx = (size_t)blockIdx.x * blockDim.x + threadIdx.x; idx < total;
         idx += (size_t)gridDim.x * blockDim.x) {
        y[idx] += bias[idx % N];
    }
}

// ---------------------------------------------------------------------------
// Sequential buffer scan over S; one thread per (b, i) channel.
//   buf_t      = buf_{t-1} * d_t + (1 - d_t) * x_t
//   combined_t = x_t * d_t + buf_t
// Loads batched 8 deep (independent of the carried buf) for MLP.
// ---------------------------------------------------------------------------
__global__ void scan_kernel(const float* __restrict__ x,
                            const float* __restrict__ decay,
                            float* __restrict__ combined) {
    const int i = blockIdx.x * blockDim.x + threadIdx.x;  // 0..IDIM-1
    const int b = blockIdx.y;
    const size_t base = (size_t)b * SDIM * IDIM + i;

    float buf = 0.0f;
    for (int t0 = 0; t0 < SDIM; t0 += 8) {
        float d[8], xv[8];
#pragma unroll
        for (int j = 0; j < 8; j++) {
            const size_t idx = base + (size_t)(t0 + j) * IDIM;
            d[j]  = decay[idx];
            xv[j] = x[idx];
        }
#pragma unroll
        for (int j = 0; j < 8; j++) {
            buf = buf * d[j] + (1.0f - d[j]) * xv[j];
            combined[base + (size_t)(t0 + j) * IDIM] = xv[j] * d[j] + buf;
        }
    }
}

// ---------------------------------------------------------------------------
// Launch
// ---------------------------------------------------------------------------
extern "C" void kernel_launch(void* const* d_in, const int* in_sizes, int n_in,
                              void* d_out, int out_size) {
    (void)in_sizes; (void)n_in; (void)out_size;
    const float* x  = (const float*)d_in[0];
    const float* W1 = (const float*)d_in[1];
    const float* b1 = (const float*)d_in[2];
    const float* W2 = (const float*)d_in[3];
    const float* b2 = (const float*)d_in[4];
    const float* Wg = (const float*)d_in[5];
    const float* bg = (const float*)d_in[6];
    float* out = (float*)d_out;

    void *pd, *pc, *ph;
    cudaGetSymbolAddress(&pd, g_decay);
    cudaGetSymbolAddress(&pc, g_combined);
    cudaGetSymbolAddress(&ph, g_hidden);
    float* decay    = (float*)pd;
    float* combined = (float*)pc;
    float* hidden   = (float*)ph;

    // 1) gate logits: decay = x @ Wg^T   [M=16384, N=1024, K=1024]
    gemm_tf32<128, 64, 16><<<dim3(IDIM / 64, MDIM / 128), 256>>>(
        x, Wg, decay, MDIM, IDIM, IDIM);
    // 2) decay = sigmoid(logits + bg)
    ep_sigmoid<IDIM><<<2048, 256>>>(decay, bg, (size_t)MDIM * IDIM);
    // 3) sequential recurrence -> combined
    scan_kernel<<<dim3(IDIM / 128, BSZ), 128>>>(x, decay, combined);
    // 4) hidden = combined @ W1^T   [M, N=4096, K=1024]
    gemm_tf32<128, 64, 16><<<dim3(HDIM / 64, MDIM / 128), 256>>>(
        combined, W1, hidden, MDIM, HDIM, IDIM);
    // 5) hidden = relu(hidden + b1)
    ep_bias_relu<HDIM><<<4096, 256>>>(hidden, b1, (size_t)MDIM * HDIM);
    // 6) out = hidden @ W2^T   [M, N=1024, K=4096]
    gemm_tf32<128, 64, 16><<<dim3(ODIM / 64, MDIM / 128), 256>>>(
        hidden, W2, out, MDIM, ODIM, HDIM);
    // 7) out += b2
    ep_bias<ODIM><<<2048, 256>>>(out, b2, (size_t)MDIM * ODIM);
}

// round 3
// speedup vs baseline: 1.4371x; 1.4371x over previous
#include <cuda_runtime.h>
#include <cstdint>
#include <mma.h>

using namespace nvcuda;

// Problem dims (fixed by reference)
#define BSZ  8
#define SDIM 2048
#define IDIM 1024
#define HDIM 4096
#define ODIM 1024
#define MDIM (BSZ * SDIM)   // 16384

// Scratch (no cudaMalloc allowed)
__device__ float g_decay[(size_t)MDIM * IDIM];     // 64 MB
__device__ float g_combined[(size_t)MDIM * IDIM];  // 64 MB
__device__ float g_hidden[(size_t)MDIM * HDIM];    // 256 MB

// ---------------------------------------------------------------------------
// Fused TF32 GEMM + epilogue: C[m,n] = act(sum_k A[m,k]*B[n,k] + bias[n])
// A row-major [M,K], B row-major [N,K].
// Block tile 128x128x16, 256 threads, 8 warps (2 x 4), warp tile 64x32.
// cp.async double-buffered smem, rows padded to 20 floats (kills stride-16
// bank aliasing).
// ---------------------------------------------------------------------------
#define BM 128
#define BN 128
#define BK 16
#define PAD 20                       // padded row stride (floats)
#define TILE_F (BM * PAD)            // 2560 floats per operand tile
#define BUF_F (2 * TILE_F)           // A+B per buffer

enum { EP_BIAS = 0, EP_RELU = 1, EP_SIGMOID = 2 };

__device__ __forceinline__ void cp_async16(float* s, const float* g) {
    unsigned int sa = (unsigned int)__cvta_generic_to_shared(s);
    asm volatile("cp.async.cg.shared.global [%0], [%1], 16;\n" ::"r"(sa),
                 "l"(g));
}
__device__ __forceinline__ void cp_commit() {
    asm volatile("cp.async.commit_group;\n");
}
__device__ __forceinline__ void cp_wait0() {
    asm volatile("cp.async.wait_group 0;\n");
}

template <int EP>
__global__ void __launch_bounds__(256) gemm_ep(const float* __restrict__ A,
                                               const float* __restrict__ B,
                                               float* __restrict__ C,
                                               const float* __restrict__ bias,
                                               int M, int N, int K) {
    __shared__ __align__(16) float smem[2 * BUF_F];  // 40 KB

    const int tid  = threadIdx.x;
    const int warp = tid >> 5;
    const int lane = tid & 31;
    const int wm   = warp >> 2;  // 0..1 -> 64 rows
    const int wn   = warp & 3;   // 0..3 -> 32 cols
    const int bm   = blockIdx.y * BM;
    const int bn   = blockIdx.x * BN;

    wmma::fragment<wmma::accumulator, 16, 16, 8, float> c[4][2];
#pragma unroll
    for (int i = 0; i < 4; i++)
#pragma unroll
        for (int j = 0; j < 2; j++) wmma::fill_fragment(c[i][j], 0.0f);

    auto load_tile = [&](int buf, int k0) {
        float* As = smem + buf * BUF_F;
        float* Bs = As + TILE_F;
#pragma unroll
        for (int t = 0; t < 2; t++) {
            int ch = tid + t * 256;          // 0..511
            int r  = ch >> 2;                // 0..127
            int cc = (ch & 3) * 4;           // 0,4,8,12
            cp_async16(As + r * PAD + cc, A + (size_t)(bm + r) * K + k0 + cc);
            cp_async16(Bs + r * PAD + cc, B + (size_t)(bn + r) * K + k0 + cc);
        }
    };

    const int nk = K / BK;
    int buf = 0;
    load_tile(0, 0);
    cp_commit();

    for (int kt = 0; kt < nk; kt++) {
        cp_wait0();
        __syncthreads();
        if (kt + 1 < nk) {
            load_tile(buf ^ 1, (kt + 1) * BK);
            cp_commit();
        }
        const float* As = smem + buf * BUF_F;
        const float* Bs = As + TILE_F;
#pragma unroll
        for (int kk = 0; kk < BK; kk += 8) {
            wmma::fragment<wmma::matrix_a, 16, 16, 8, wmma::precision::tf32,
                           wmma::row_major> a[4];
            wmma::fragment<wmma::matrix_b, 16, 16, 8, wmma::precision::tf32,
                           wmma::col_major> b[2];
#pragma unroll
            for (int i = 0; i < 4; i++) {
                wmma::load_matrix_sync(a[i], As + (wm * 64 + i * 16) * PAD + kk,
                                       PAD);
#pragma unroll
                for (int e = 0; e < a[i].num_elements; e++)
                    a[i].x[e] = wmma::__float_to_tf32(a[i].x[e]);
            }
#pragma unroll
            for (int j = 0; j < 2; j++) {
                wmma::load_matrix_sync(b[j], Bs + (wn * 32 + j * 16) * PAD + kk,
                                       PAD);
#pragma unroll
                for (int e = 0; e < b[j].num_elements; e++)
                    b[j].x[e] = wmma::__float_to_tf32(b[j].x[e]);
            }
#pragma unroll
            for (int i = 0; i < 4; i++)
#pragma unroll
                for (int j = 0; j < 2; j++)
                    wmma::mma_sync(c[i][j], a[i], b[j], c[i][j]);
        }
        buf ^= 1;
        __syncthreads();  // all reads of this buffer done before it is refilled
    }

    // ------------------ fused epilogue via per-warp smem staging -----------
    __syncthreads();
    float* stage = smem + warp * (16 * PAD);  // 320 floats per warp
#pragma unroll
    for (int j = 0; j < 2; j++) {
        const int colbase = bn + wn * 32 + j * 16;
#pragma unroll
        for (int i = 0; i < 4; i++) {
            wmma::store_matrix_sync(stage, c[i][j], PAD, wmma::mem_row_major);
            __syncwarp();
            const int r  = lane >> 1;          // 0..15
            const int cg = (lane & 1) * 8;     // 0 or 8
            float v[8];
#pragma unroll
            for (int e = 0; e < 8; e++) {
                float t = stage[r * PAD + cg + e] + __ldg(&bias[colbase + cg + e]);
                if (EP == EP_RELU)
                    t = fmaxf(t, 0.0f);
                else if (EP == EP_SIGMOID)
                    t = 1.0f / (1.0f + __expf(-t));
                v[e] = t;
            }
            const size_t off =
                (size_t)(bm + wm * 64 + i * 16 + r) * N + colbase + cg;
            *(float4*)&C[off]     = make_float4(v[0], v[1], v[2], v[3]);
            *(float4*)&C[off + 4] = make_float4(v[4], v[5], v[6], v[7]);
            __syncwarp();
        }
    }
}

// ---------------------------------------------------------------------------
// Sequential buffer scan over S; one thread per (b, i) channel.
//   buf_t      = buf_{t-1} * d_t + (1 - d_t) * x_t
//   combined_t = x_t * d_t + buf_t
// ---------------------------------------------------------------------------
__global__ void scan_kernel(const float* __restrict__ x,
                            const float* __restrict__ decay,
                            float* __restrict__ combined) {
    const int i = blockIdx.x * blockDim.x + threadIdx.x;  // 0..IDIM-1
    const int b = blockIdx.y;
    const size_t base = (size_t)b * SDIM * IDIM + i;

    float buf = 0.0f;
    for (int t0 = 0; t0 < SDIM; t0 += 8) {
        float d[8], xv[8];
#pragma unroll
        for (int j = 0; j < 8; j++) {
            const size_t idx = base + (size_t)(t0 + j) * IDIM;
            d[j]  = decay[idx];
            xv[j] = x[idx];
        }
#pragma unroll
        for (int j = 0; j < 8; j++) {
            buf = buf * d[j] + (1.0f - d[j]) * xv[j];
            combined[base + (size_t)(t0 + j) * IDIM] = xv[j] * d[j] + buf;
        }
    }
}

// ---------------------------------------------------------------------------
// Launch: gate GEMM(+sigmoid) -> scan -> MLP1(+relu) -> MLP2(+bias -> d_out)
// ---------------------------------------------------------------------------
extern "C" void kernel_launch(void* const* d_in, const int* in_sizes, int n_in,
                              void* d_out, int out_size) {
    (void)in_sizes; (void)n_in; (void)out_size;
    const float* x  = (const float*)d_in[0];
    const float* W1 = (const float*)d_in[1];
    const float* b1 = (const float*)d_in[2];
    const float* W2 = (const float*)d_in[3];
    const float* b2 = (const float*)d_in[4];
    const float* Wg = (const float*)d_in[5];
    const float* bg = (const float*)d_in[6];
    float* out = (float*)d_out;

    void *pd, *pc, *ph;
    cudaGetSymbolAddress(&pd, g_decay);
    cudaGetSymbolAddress(&pc, g_combined);
    cudaGetSymbolAddress(&ph, g_hidden);
    float* decay    = (float*)pd;
    float* combined = (float*)pc;
    float* hidden   = (float*)ph;

    // 1) decay = sigmoid(x @ Wg^T + bg)
    gemm_ep<EP_SIGMOID><<<dim3(IDIM / BN, MDIM / BM), 256>>>(
        x, Wg, decay, bg, MDIM, IDIM, IDIM);
    // 2) sequential recurrence -> combined
    scan_kernel<<<dim3(IDIM / 128, BSZ), 128>>>(x, decay, combined);
    // 3) hidden = relu(combined @ W1^T + b1)
    gemm_ep<EP_RELU><<<dim3(HDIM / BN, MDIM / BM), 256>>>(
        combined, W1, hidden, b1, MDIM, HDIM, IDIM);
    // 4) out = hidden @ W2^T + b2
    gemm_ep<EP_BIAS><<<dim3(ODIM / BN, MDIM / BM), 256>>>(
        hidden, W2, out, b2, MDIM, ODIM, HDIM);
}

// round 5
// speedup vs baseline: 5.4278x; 3.7769x over previous
#include <cuda_runtime.h>
#include <cstdint>
#include <mma.h>

// Problem dims (fixed by reference)
#define BSZ  8
#define SDIM 2048
#define IDIM 1024
#define HDIM 4096
#define ODIM 1024
#define MDIM (BSZ * SDIM)   // 16384

// Scratch (no cudaMalloc allowed)
__device__ float g_decay[(size_t)MDIM * IDIM];     // 64 MB
__device__ float g_combined[(size_t)MDIM * IDIM];  // 64 MB (tf32-rounded)
__device__ float g_hidden[(size_t)MDIM * HDIM];    // 256 MB (tf32-rounded)
__device__ float g_xr[(size_t)MDIM * IDIM];        // 64 MB (tf32-rounded x)
__device__ float g_wgr[(size_t)IDIM * IDIM];       // 4 MB
__device__ float g_w1r[(size_t)HDIM * IDIM];       // 16 MB
__device__ float g_w2r[(size_t)ODIM * HDIM];       // 16 MB

// tcgen05 only exists in the arch-specific (sm_103a) compilation pass. The
// plain compute_103 pass gets a wmma fallback body for the same kernels.
#if !defined(__CUDA_ARCH__) || defined(__CUDA_ARCH_FEAT_SM103_ALL) || \
    defined(__CUDA_ARCH_FEAT_SM100_ALL) || defined(__CUDA_ARCH_SPECIFIC__)
#define KUSE_TC 1
#else
#define KUSE_TC 0
#endif

// ---------------------------------------------------------------------------
// Common helpers (valid on all targets)
// ---------------------------------------------------------------------------
__device__ __forceinline__ uint32_t smem_u32(const void* p) {
    return (uint32_t)__cvta_generic_to_shared(p);
}
__device__ __forceinline__ float to_tf32(float x) {
    float r;
    asm("cvt.rna.tf32.f32 %0, %1;" : "=f"(r) : "f"(x));
    return r;
}
__device__ __forceinline__ void cp16(uint32_t s, const void* g) {
    asm volatile("cp.async.cg.shared.global [%0], [%1], 16;" ::"r"(s), "l"(g));
}

#if KUSE_TC
// ---------------------------------------------------------------------------
// tcgen05-only helpers
// ---------------------------------------------------------------------------
__device__ __forceinline__ void mbar_init(uint32_t a, uint32_t cnt) {
    asm volatile("mbarrier.init.shared.b64 [%0], %1;" ::"r"(a), "r"(cnt)
                 : "memory");
}
__device__ __forceinline__ void mbar_wait(uint32_t a, uint32_t parity) {
    asm volatile(
        "{\n\t.reg .pred P;\n"
        "W%=:\n\t"
        "mbarrier.try_wait.parity.acquire.cta.shared::cta.b64 P, [%0], %1, 0x989680;\n\t"
        "@P bra D%=;\n\t"
        "bra W%=;\n"
        "D%=:\n\t}"
        ::"r"(a), "r"(parity)
        : "memory");
}
__device__ __forceinline__ void mma_tf32(uint32_t d, uint64_t ad, uint64_t bd,
                                         uint32_t idesc, bool acc) {
    uint32_t en = acc ? 1u : 0u;
    asm volatile(
        "{\n\t.reg .pred p;\n\t"
        "setp.ne.u32 p, %4, 0;\n\t"
        "tcgen05.mma.cta_group::1.kind::tf32 [%0], %1, %2, %3, {%5,%5,%5,%5}, p;\n\t}"
        ::"r"(d), "l"(ad), "l"(bd), "r"(idesc), "r"(en), "r"(0u)
        : "memory");
}
#define LDTM_X32(r, a)                                                       \
    asm volatile(                                                            \
        "tcgen05.ld.sync.aligned.32x32b.x32.b32 "                            \
        "{%0,%1,%2,%3,%4,%5,%6,%7,%8,%9,%10,%11,%12,%13,%14,%15,"            \
        "%16,%17,%18,%19,%20,%21,%22,%23,%24,%25,%26,%27,%28,%29,%30,%31}, " \
        "[%32];"                                                             \
        : "=r"((r)[0]), "=r"((r)[1]), "=r"((r)[2]), "=r"((r)[3]),            \
          "=r"((r)[4]), "=r"((r)[5]), "=r"((r)[6]), "=r"((r)[7]),            \
          "=r"((r)[8]), "=r"((r)[9]), "=r"((r)[10]), "=r"((r)[11]),          \
          "=r"((r)[12]), "=r"((r)[13]), "=r"((r)[14]), "=r"((r)[15]),        \
          "=r"((r)[16]), "=r"((r)[17]), "=r"((r)[18]), "=r"((r)[19]),        \
          "=r"((r)[20]), "=r"((r)[21]), "=r"((r)[22]), "=r"((r)[23]),        \
          "=r"((r)[24]), "=r"((r)[25]), "=r"((r)[26]), "=r"((r)[27]),        \
          "=r"((r)[28]), "=r"((r)[29]), "=r"((r)[30]), "=r"((r)[31])         \
        : "r"(a))
#endif  // KUSE_TC

// ---------------------------------------------------------------------------
// GEMM: C[m,n] = act(sum_k A[m,k]*B[n,k] + bias[n])
// A [M,K] row-major, B [N,K] row-major, both pre-rounded to tf32.
// ---------------------------------------------------------------------------
#define BM 128
#define BN 128
#define TBYTES 16384          // 128 rows x 128 bytes
#define STAGES 4
#define SMEM_REQ (STAGES * 2 * TBYTES + 1024 + 64)

static constexpr uint64_t DESC_BASE =
    (2ull << 61) | (1ull << 46) | (64ull << 32) | (1ull << 16);  // SW128 K-major
// idesc: dtype F32, atype/btype TF32(2), N=128, M=128
#define IDESC ((1u << 4) | (2u << 7) | (2u << 10) | (16u << 17) | (8u << 24))

enum { EP_SIG = 0, EP_RELU = 1, EP_BIAS = 2 };

template <int EP, bool ROUND>
__global__ void __launch_bounds__(256, 1)
gemm_tc(const float* __restrict__ A, const float* __restrict__ B,
        float* __restrict__ C, const float* __restrict__ bias, int M, int N,
        int K) {
    extern __shared__ char dsm[];
    const int tid  = threadIdx.x;
    const int warp = tid >> 5;
    const int lane = tid & 31;
    const int bm   = blockIdx.y * BM;
    const int bn   = blockIdx.x * BN;

#if KUSE_TC
    // =================== tcgen05 path (sm_103a) ===========================
    const uint32_t sb    = smem_u32(dsm);
    const uint32_t tiles = (sb + 1023u) & ~1023u;
    const uint32_t ctrl  = tiles + STAGES * 2 * TBYTES;  // mbars + tmem ptr

    if (tid == 0) {
#pragma unroll
        for (int s = 0; s < STAGES; s++) mbar_init(ctrl + 8 * s, 1);
    }
    if (warp == 0) {
        asm volatile(
            "tcgen05.alloc.cta_group::1.sync.aligned.shared::cta.b32 [%0], %1;"
            ::"r"(ctrl + 32), "r"(128u)
            : "memory");
        asm volatile("tcgen05.relinquish_alloc_permit.cta_group::1.sync.aligned;");
    }
    __syncthreads();
    uint32_t tmem;
    asm volatile("ld.shared.b32 %0, [%1];" : "=r"(tmem) : "r"(ctrl + 32));

    const int nk = K >> 5;  // 32-float k-tiles

    auto load_tile = [&](int st, int kt) {
        const uint32_t As = tiles + st * 2 * TBYTES;
        const uint32_t Bs = As + TBYTES;
        const float* Ag = A + (size_t)bm * K + kt * 32;
        const float* Bg = B + (size_t)bn * K + kt * 32;
#pragma unroll
        for (int t = 0; t < 4; t++) {
            const int ch = tid + t * 256;   // 0..1023
            const int r  = ch >> 3;         // row 0..127
            const int c  = ch & 7;          // 16B chunk 0..7
            uint32_t off = (uint32_t)(r * 128 + c * 16);
            off ^= (off >> 3) & 0x70;       // SW128 swizzle
            cp16(As + off, Ag + (size_t)r * K + c * 4);
            cp16(Bs + off, Bg + (size_t)r * K + c * 4);
        }
        asm volatile("cp.async.commit_group;");
    };

#pragma unroll
    for (int s = 0; s < STAGES - 1; s++) load_tile(s, s);

    for (int kt = 0; kt < nk; kt++) {
        asm volatile("cp.async.wait_group 2;");  // tile kt resident
        __syncthreads();
        asm volatile("fence.proxy.async.shared::cta;" ::: "memory");
        if (tid == 0) {
            const uint32_t As = tiles + (kt % STAGES) * 2 * TBYTES;
            const uint64_t ad = DESC_BASE | ((uint64_t)(As >> 4) & 0x3FFF);
            const uint64_t bd =
                DESC_BASE | ((uint64_t)((As + TBYTES) >> 4) & 0x3FFF);
#pragma unroll
            for (int s = 0; s < 4; s++)  // 4 x K=8 steps (+32B each)
                mma_tf32(tmem, ad + 2 * s, bd + 2 * s, IDESC,
                         (kt > 0) || (s > 0));
            asm volatile(
                "tcgen05.commit.cta_group::1.mbarrier::arrive::one.shared::cluster.b64 [%0];"
                ::"r"(ctrl + 8 * (kt % STAGES))
                : "memory");
        }
        const int tl = kt + STAGES - 1;
        if (tl < nk) {
            if (tl >= STAGES)  // wait MMA that last used this buffer
                mbar_wait(ctrl + 8 * (tl % STAGES),
                          (uint32_t)(((tl / STAGES) - 1) & 1));
            load_tile(tl % STAGES, tl);
        } else {
            asm volatile("cp.async.commit_group;");  // keep group count moving
        }
    }

    // drain: wait for final tile's MMAs (commit implies all prior complete)
    mbar_wait(ctrl + 8 * ((nk - 1) % STAGES),
              (uint32_t)(((nk / STAGES) - 1) & 1));
    asm volatile("tcgen05.fence::after_thread_sync;" ::: "memory");

    // ---------------- epilogue: TMEM -> bias/act -> gmem -------------------
    const int wg  = warp >> 2;  // 0..1 -> col half
    const int wq  = warp & 3;   // lane partition
    const uint32_t tpart = tmem + ((uint32_t)wq << 21);
    const int row = bm + wq * 32 + lane;
#pragma unroll
    for (int h = 0; h < 2; h++) {
        const int col0 = wg * 64 + h * 32;
        uint32_t r[32];
        LDTM_X32(r, tpart + col0);
        asm volatile("tcgen05.wait::ld.sync.aligned;" ::: "memory");
        float v[32];
#pragma unroll
        for (int j = 0; j < 32; j++) {
            float t = __uint_as_float(r[j]) + __ldg(&bias[bn + col0 + j]);
            if (EP == EP_RELU) t = fmaxf(t, 0.0f);
            if (EP == EP_SIG) t = 1.0f / (1.0f + __expf(-t));
            if (ROUND) t = to_tf32(t);
            v[j] = t;
        }
        float* dst = &C[(size_t)row * N + bn + col0];
#pragma unroll
        for (int q = 0; q < 8; q++)
            *(float4*)&dst[q * 4] =
                make_float4(v[q * 4], v[q * 4 + 1], v[q * 4 + 2], v[q * 4 + 3]);
    }

    __syncthreads();
    if (warp == 0)
        asm volatile("tcgen05.dealloc.cta_group::1.sync.aligned.b32 %0, %1;"
                     ::"r"(tmem), "r"(128u));

#else
    // =================== wmma fallback (plain sm_103 pass) ================
    using namespace nvcuda;
    constexpr int BKW = 16, PADW = 20;
    constexpr int TILE_F = BM * PADW;     // 2560 floats
    constexpr int BUF_F  = 2 * TILE_F;
    float* smemf = (float*)dsm;           // uses 2*BUF_F floats = 40 KB

    const int wm = warp >> 2;  // 0..1 -> 64 rows
    const int wn = warp & 3;   // 0..3 -> 32 cols

    wmma::fragment<wmma::accumulator, 16, 16, 8, float> c[4][2];
#pragma unroll
    for (int i = 0; i < 4; i++)
#pragma unroll
        for (int j = 0; j < 2; j++) wmma::fill_fragment(c[i][j], 0.0f);

    auto load_tile = [&](int buf, int k0) {
        float* As = smemf + buf * BUF_F;
        float* Bs = As + TILE_F;
#pragma unroll
        for (int t = 0; t < 2; t++) {
            int ch = tid + t * 256;
            int r  = ch >> 2;
            int cc = (ch & 3) * 4;
            cp16(smem_u32(As + r * PADW + cc), A + (size_t)(bm + r) * K + k0 + cc);
            cp16(smem_u32(Bs + r * PADW + cc), B + (size_t)(bn + r) * K + k0 + cc);
        }
        asm volatile("cp.async.commit_group;");
    };

    const int nk = K / BKW;
    int buf = 0;
    load_tile(0, 0);

    for (int kt = 0; kt < nk; kt++) {
        asm volatile("cp.async.wait_group 0;");
        __syncthreads();
        if (kt + 1 < nk) load_tile(buf ^ 1, (kt + 1) * BKW);
        const float* As = smemf + buf * BUF_F;
        const float* Bs = As + TILE_F;
#pragma unroll
        for (int kk = 0; kk < BKW; kk += 8) {
            wmma::fragment<wmma::matrix_a, 16, 16, 8, wmma::precision::tf32,
                           wmma::row_major> a[4];
            wmma::fragment<wmma::matrix_b, 16, 16, 8, wmma::precision::tf32,
                           wmma::col_major> b[2];
#pragma unroll
            for (int i = 0; i < 4; i++) {
                wmma::load_matrix_sync(a[i], As + (wm * 64 + i * 16) * PADW + kk,
                                       PADW);
#pragma unroll
                for (int e = 0; e < a[i].num_elements; e++)
                    a[i].x[e] = wmma::__float_to_tf32(a[i].x[e]);
            }
#pragma unroll
            for (int j = 0; j < 2; j++) {
                wmma::load_matrix_sync(b[j], Bs + (wn * 32 + j * 16) * PADW + kk,
                                       PADW);
#pragma unroll
                for (int e = 0; e < b[j].num_elements; e++)
                    b[j].x[e] = wmma::__float_to_tf32(b[j].x[e]);
            }
#pragma unroll
            for (int i = 0; i < 4; i++)
#pragma unroll
                for (int j = 0; j < 2; j++)
                    wmma::mma_sync(c[i][j], a[i], b[j], c[i][j]);
        }
        buf ^= 1;
        __syncthreads();
    }

    __syncthreads();
    float* stage = smemf + warp * (16 * PADW);
#pragma unroll
    for (int j = 0; j < 2; j++) {
        const int colbase = bn + wn * 32 + j * 16;
#pragma unroll
        for (int i = 0; i < 4; i++) {
            wmma::store_matrix_sync(stage, c[i][j], PADW, wmma::mem_row_major);
            __syncwarp();
            const int r  = lane >> 1;
            const int cg = (lane & 1) * 8;
            float v[8];
#pragma unroll
            for (int e = 0; e < 8; e++) {
                float t = stage[r * PADW + cg + e] + __ldg(&bias[colbase + cg + e]);
                if (EP == EP_RELU) t = fmaxf(t, 0.0f);
                if (EP == EP_SIG) t = 1.0f / (1.0f + __expf(-t));
                if (ROUND) t = to_tf32(t);
                v[e] = t;
            }
            const size_t off =
                (size_t)(bm + wm * 64 + i * 16 + r) * N + colbase + cg;
            *(float4*)&C[off]     = make_float4(v[0], v[1], v[2], v[3]);
            *(float4*)&C[off + 4] = make_float4(v[4], v[5], v[6], v[7]);
            __syncwarp();
        }
    }
#endif  // KUSE_TC
}

// ---------------------------------------------------------------------------
// Round-to-nearest tf32 prep
// ---------------------------------------------------------------------------
__global__ void round_kernel(const float* __restrict__ in,
                             float* __restrict__ out, size_t n) {
    for (size_t i = (size_t)blockIdx.x * blockDim.x + threadIdx.x; i < n;
         i += (size_t)gridDim.x * blockDim.x)
        out[i] = to_tf32(in[i]);
}

// ---------------------------------------------------------------------------
// Sequential buffer scan; combined is tf32-rounded (GEMM A input).
// ---------------------------------------------------------------------------
__global__ void scan_kernel(const float* __restrict__ x,
                            const float* __restrict__ decay,
                            float* __restrict__ combined) {
    const int i = blockIdx.x * blockDim.x + threadIdx.x;
    const int b = blockIdx.y;
    const size_t base = (size_t)b * SDIM * IDIM + i;

    float buf = 0.0f;
    for (int t0 = 0; t0 < SDIM; t0 += 8) {
        float d[8], xv[8];
#pragma unroll
        for (int j = 0; j < 8; j++) {
            const size_t idx = base + (size_t)(t0 + j) * IDIM;
            d[j]  = decay[idx];
            xv[j] = x[idx];
        }
#pragma unroll
        for (int j = 0; j < 8; j++) {
            buf = buf * d[j] + (1.0f - d[j]) * xv[j];
            combined[base + (size_t)(t0 + j) * IDIM] = to_tf32(xv[j] * d[j] + buf);
        }
    }
}

// ---------------------------------------------------------------------------
// Launch
// ---------------------------------------------------------------------------
extern "C" void kernel_launch(void* const* d_in, const int* in_sizes, int n_in,
                              void* d_out, int out_size) {
    (void)in_sizes; (void)n_in; (void)out_size;
    const float* x  = (const float*)d_in[0];
    const float* W1 = (const float*)d_in[1];
    const float* b1 = (const float*)d_in[2];
    const float* W2 = (const float*)d_in[3];
    const float* b2 = (const float*)d_in[4];
    const float* Wg = (const float*)d_in[5];
    const float* bg = (const float*)d_in[6];
    float* out = (float*)d_out;

    void *pd, *pc, *ph, *pxr, *pwg, *pw1, *pw2;
    cudaGetSymbolAddress(&pd, g_decay);
    cudaGetSymbolAddress(&pc, g_combined);
    cudaGetSymbolAddress(&ph, g_hidden);
    cudaGetSymbolAddress(&pxr, g_xr);
    cudaGetSymbolAddress(&pwg, g_wgr);
    cudaGetSymbolAddress(&pw1, g_w1r);
    cudaGetSymbolAddress(&pw2, g_w2r);
    float* decay    = (float*)pd;
    float* combined = (float*)pc;
    float* hidden   = (float*)ph;
    float* xr       = (float*)pxr;
    float* wgr      = (float*)pwg;
    float* w1r      = (float*)pw1;
    float* w2r      = (float*)pw2;

    cudaFuncSetAttribute(gemm_tc<EP_SIG, false>,
                         cudaFuncAttributeMaxDynamicSharedMemorySize, SMEM_REQ);
    cudaFuncSetAttribute(gemm_tc<EP_RELU, true>,
                         cudaFuncAttributeMaxDynamicSharedMemorySize, SMEM_REQ);
    cudaFuncSetAttribute(gemm_tc<EP_BIAS, false>,
                         cudaFuncAttributeMaxDynamicSharedMemorySize, SMEM_REQ);

    // tf32 round-to-nearest prep (weights + x)
    round_kernel<<<1024, 256>>>(x, xr, (size_t)MDIM * IDIM);
    round_kernel<<<256, 256>>>(Wg, wgr, (size_t)IDIM * IDIM);
    round_kernel<<<512, 256>>>(W1, w1r, (size_t)HDIM * IDIM);
    round_kernel<<<512, 256>>>(W2, w2r, (size_t)ODIM * HDIM);

    // 1) decay = sigmoid(x @ Wg^T + bg)
    gemm_tc<EP_SIG, false><<<dim3(IDIM / BN, MDIM / BM), 256, SMEM_REQ>>>(
        xr, wgr, decay, bg, MDIM, IDIM, IDIM);
    // 2) recurrence -> combined (tf32-rounded)
    scan_kernel<<<dim3(IDIM / 128, BSZ), 128>>>(x, decay, combined);
    // 3) hidden = relu(combined @ W1^T + b1), tf32-rounded
    gemm_tc<EP_RELU, true><<<dim3(HDIM / BN, MDIM / BM), 256, SMEM_REQ>>>(
        combined, w1r, hidden, b1, MDIM, HDIM, IDIM);
    // 4) out = hidden @ W2^T + b2
    gemm_tc<EP_BIAS, false><<<dim3(ODIM / BN, MDIM / BM), 256, SMEM_REQ>>>(
        hidden, w2r, out, b2, MDIM, ODIM, HDIM);
}

// round 6
// speedup vs baseline: 6.8856x; 1.2686x over previous
#include <cuda_runtime.h>
#include <cstdint>

// Problem dims (fixed by reference)
#define BSZ  8
#define SDIM 2048
#define IDIM 1024
#define HDIM 4096
#define ODIM 1024
#define MDIM (BSZ * SDIM)   // 16384

// Scratch (no cudaMalloc allowed)
__device__ float g_decay[(size_t)MDIM * IDIM];     // 64 MB
__device__ float g_combined[(size_t)MDIM * IDIM];  // 64 MB (tf32-rounded)
__device__ float g_hidden[(size_t)MDIM * HDIM];    // 256 MB (tf32-rounded)
__device__ float g_xr[(size_t)MDIM * IDIM];        // 64 MB (tf32-rounded x)
__device__ float g_wgr[(size_t)IDIM * IDIM];       // 4 MB
__device__ float g_w1r[(size_t)HDIM * IDIM];       // 16 MB
__device__ float g_w2r[(size_t)ODIM * HDIM];       // 16 MB

// tcgen05 only exists in the arch-specific (sm_103a) compilation pass.
#if !defined(__CUDA_ARCH__) || defined(__CUDA_ARCH_FEAT_SM103_ALL) || \
    defined(__CUDA_ARCH_FEAT_SM100_ALL) || defined(__CUDA_ARCH_SPECIFIC__)
#define KUSE_TC 1
#else
#define KUSE_TC 0
#endif

// ---------------------------------------------------------------------------
// Common helpers
// ---------------------------------------------------------------------------
__device__ __forceinline__ uint32_t smem_u32(const void* p) {
    return (uint32_t)__cvta_generic_to_shared(p);
}
__device__ __forceinline__ float to_tf32(float x) {
    float r;
    asm("cvt.rna.tf32.f32 %0, %1;" : "=f"(r) : "f"(x));
    return r;
}
__device__ __forceinline__ void cp16(uint32_t s, const void* g) {
    asm volatile("cp.async.cg.shared.global [%0], [%1], 16;" ::"r"(s), "l"(g));
}

#if KUSE_TC
__device__ __forceinline__ void mbar_init(uint32_t a, uint32_t cnt) {
    asm volatile("mbarrier.init.shared.b64 [%0], %1;" ::"r"(a), "r"(cnt)
                 : "memory");
}
__device__ __forceinline__ void mbar_wait(uint32_t a, uint32_t parity) {
    asm volatile(
        "{\n\t.reg .pred P;\n"
        "W%=:\n\t"
        "mbarrier.try_wait.parity.acquire.cta.shared::cta.b64 P, [%0], %1, 0x989680;\n\t"
        "@P bra D%=;\n\t"
        "bra W%=;\n"
        "D%=:\n\t}"
        ::"r"(a), "r"(parity)
        : "memory");
}
__device__ __forceinline__ void mma_tf32(uint32_t d, uint64_t ad, uint64_t bd,
                                         uint32_t idesc, bool acc) {
    uint32_t en = acc ? 1u : 0u;
    asm volatile(
        "{\n\t.reg .pred p;\n\t"
        "setp.ne.u32 p, %4, 0;\n\t"
        "tcgen05.mma.cta_group::1.kind::tf32 [%0], %1, %2, %3, {%5,%5,%5,%5}, p;\n\t}"
        ::"r"(d), "l"(ad), "l"(bd), "r"(idesc), "r"(en), "r"(0u)
        : "memory");
}
#define LDTM_X32(r, a)                                                       \
    asm volatile(                                                            \
        "tcgen05.ld.sync.aligned.32x32b.x32.b32 "                            \
        "{%0,%1,%2,%3,%4,%5,%6,%7,%8,%9,%10,%11,%12,%13,%14,%15,"            \
        "%16,%17,%18,%19,%20,%21,%22,%23,%24,%25,%26,%27,%28,%29,%30,%31}, " \
        "[%32];"                                                             \
        : "=r"((r)[0]), "=r"((r)[1]), "=r"((r)[2]), "=r"((r)[3]),            \
          "=r"((r)[4]), "=r"((r)[5]), "=r"((r)[6]), "=r"((r)[7]),            \
          "=r"((r)[8]), "=r"((r)[9]), "=r"((r)[10]), "=r"((r)[11]),          \
          "=r"((r)[12]), "=r"((r)[13]), "=r"((r)[14]), "=r"((r)[15]),        \
          "=r"((r)[16]), "=r"((r)[17]), "=r"((r)[18]), "=r"((r)[19]),        \
          "=r"((r)[20]), "=r"((r)[21]), "=r"((r)[22]), "=r"((r)[23]),        \
          "=r"((r)[24]), "=r"((r)[25]), "=r"((r)[26]), "=r"((r)[27]),        \
          "=r"((r)[28]), "=r"((r)[29]), "=r"((r)[30]), "=r"((r)[31])         \
        : "r"(a))
#endif  // KUSE_TC

// ---------------------------------------------------------------------------
// GEMM: C[m,n] = act(sum_k A[m,k]*B[n,k] + bias[n])
// A [M,K] row-major, B [N,K] row-major, both pre-rounded to tf32.
// CTA tile 128x256, BK=32 (128B rows, SW128), 4-stage cp.async pipeline.
// ---------------------------------------------------------------------------
#define BM 128
#define BN 256
#define TB_A 16384            // 128 rows x 128 bytes
#define TB_B 32768            // 256 rows x 128 bytes
#define TB_ST (TB_A + TB_B)   // 48 KB per stage
#define STAGES 4
#define SMEM_REQ (STAGES * TB_ST + 1024 + 64)

static constexpr uint64_t DESC_BASE =
    (2ull << 61) | (1ull << 46) | (64ull << 32) | (1ull << 16);  // SW128 K-major
// idesc: dtype F32, atype/btype TF32(2), N=256, M=128
#define IDESC ((1u << 4) | (2u << 7) | (2u << 10) | (32u << 17) | (8u << 24))

enum { EP_SIG = 0, EP_RELU = 1, EP_BIAS = 2 };

template <int EP, bool ROUND>
__global__ void __launch_bounds__(256, 1)
gemm_tc(const float* __restrict__ A, const float* __restrict__ B,
        float* __restrict__ C, const float* __restrict__ bias, int M, int N,
        int K) {
    extern __shared__ char dsm[];
    const int tid  = threadIdx.x;
    const int warp = tid >> 5;
    const int lane = tid & 31;
    const int bm   = blockIdx.y * BM;
    const int bn   = blockIdx.x * BN;

#if KUSE_TC
    // =================== tcgen05 path (sm_103a) ===========================
    const uint32_t sb    = smem_u32(dsm);
    const uint32_t tiles = (sb + 1023u) & ~1023u;
    const uint32_t ctrl  = tiles + STAGES * TB_ST;  // mbars + tmem ptr

    if (tid == 0) {
#pragma unroll
        for (int s = 0; s < STAGES; s++) mbar_init(ctrl + 8 * s, 1);
    }
    if (warp == 0) {
        asm volatile(
            "tcgen05.alloc.cta_group::1.sync.aligned.shared::cta.b32 [%0], %1;"
            ::"r"(ctrl + 32), "r"(256u)
            : "memory");
        asm volatile("tcgen05.relinquish_alloc_permit.cta_group::1.sync.aligned;");
    }
    __syncthreads();
    uint32_t tmem;
    asm volatile("ld.shared.b32 %0, [%1];" : "=r"(tmem) : "r"(ctrl + 32));

    const int nk = K >> 5;  // 32-float k-tiles

    auto load_tile = [&](int st, int kt) {
        const uint32_t As = tiles + st * TB_ST;
        const uint32_t Bs = As + TB_A;
        const float* Ag = A + (size_t)bm * K + kt * 32;
        const float* Bg = B + (size_t)bn * K + kt * 32;
        // A: 1024 16B-chunks (4/thread)
#pragma unroll
        for (int t = 0; t < 4; t++) {
            const int ch = tid + t * 256;
            const int r  = ch >> 3;
            const int c  = ch & 7;
            uint32_t off = (uint32_t)(r * 128 + c * 16);
            off ^= (off >> 3) & 0x70;  // SW128 swizzle
            cp16(As + off, Ag + (size_t)r * K + c * 4);
        }
        // B: 2048 16B-chunks (8/thread)
#pragma unroll
        for (int t = 0; t < 8; t++) {
            const int ch = tid + t * 256;
            const int r  = ch >> 3;
            const int c  = ch & 7;
            uint32_t off = (uint32_t)(r * 128 + c * 16);
            off ^= (off >> 3) & 0x70;
            cp16(Bs + off, Bg + (size_t)r * K + c * 4);
        }
        asm volatile("cp.async.commit_group;");
    };

#pragma unroll
    for (int s = 0; s < STAGES - 1; s++) load_tile(s, s);

    for (int kt = 0; kt < nk; kt++) {
        asm volatile("cp.async.wait_group 2;");  // tile kt resident
        __syncthreads();
        asm volatile("fence.proxy.async.shared::cta;" ::: "memory");
        if (tid == 0) {
            const uint32_t As = tiles + (kt % STAGES) * TB_ST;
            const uint64_t ad = DESC_BASE | ((uint64_t)(As >> 4) & 0x3FFF);
            const uint64_t bd =
                DESC_BASE | ((uint64_t)((As + TB_A) >> 4) & 0x3FFF);
#pragma unroll
            for (int s = 0; s < 4; s++)  // 4 x K=8 steps (+32B each)
                mma_tf32(tmem, ad + 2 * s, bd + 2 * s, IDESC,
                         (kt > 0) || (s > 0));
            asm volatile(
                "tcgen05.commit.cta_group::1.mbarrier::arrive::one.shared::cluster.b64 [%0];"
                ::"r"(ctrl + 8 * (kt % STAGES))
                : "memory");
        }
        const int tl = kt + STAGES - 1;
        if (tl < nk) {
            if (tl >= STAGES)  // wait MMA that last used this buffer
                mbar_wait(ctrl + 8 * (tl % STAGES),
                          (uint32_t)(((tl / STAGES) - 1) & 1));
            load_tile(tl % STAGES, tl);
        } else {
            asm volatile("cp.async.commit_group;");  // keep group count moving
        }
    }

    mbar_wait(ctrl + 8 * ((nk - 1) % STAGES),
              (uint32_t)(((nk / STAGES) - 1) & 1));
    asm volatile("tcgen05.fence::after_thread_sync;" ::: "memory");

    // ---------------- epilogue: TMEM -> bias/act -> gmem -------------------
    const int wg  = warp >> 2;  // 0..1 -> 128-col half
    const int wq  = warp & 3;   // lane partition (rows)
    const uint32_t tpart = tmem + ((uint32_t)wq << 21);
    const int row = bm + wq * 32 + lane;
#pragma unroll
    for (int h = 0; h < 4; h++) {
        const int col0 = wg * 128 + h * 32;
        uint32_t r[32];
        LDTM_X32(r, tpart + col0);
        asm volatile("tcgen05.wait::ld.sync.aligned;" ::: "memory");
        float v[32];
#pragma unroll
        for (int j = 0; j < 32; j++) {
            float t = __uint_as_float(r[j]) + __ldg(&bias[bn + col0 + j]);
            if (EP == EP_RELU) t = fmaxf(t, 0.0f);
            if (EP == EP_SIG) t = 1.0f / (1.0f + __expf(-t));
            if (ROUND) t = to_tf32(t);
            v[j] = t;
        }
        float* dst = &C[(size_t)row * N + bn + col0];
#pragma unroll
        for (int q = 0; q < 8; q++)
            *(float4*)&dst[q * 4] =
                make_float4(v[q * 4], v[q * 4 + 1], v[q * 4 + 2], v[q * 4 + 3]);
    }

    __syncthreads();
    if (warp == 0)
        asm volatile("tcgen05.dealloc.cta_group::1.sync.aligned.b32 %0, %1;"
                     ::"r"(tmem), "r"(256u));

#else
    // ============ naive fallback (plain sm_103 pass; never runs) ==========
    for (int e = tid; e < BM * BN; e += 256) {
        const int r  = e / BN;
        const int cc = e % BN;
        float acc = 0.0f;
        for (int k = 0; k < K; k++)
            acc += A[(size_t)(bm + r) * K + k] * B[(size_t)(bn + cc) * K + k];
        float t = acc + bias[bn + cc];
        if (EP == EP_RELU) t = fmaxf(t, 0.0f);
        if (EP == EP_SIG) t = 1.0f / (1.0f + __expf(-t));
        if (ROUND) t = to_tf32(t);
        C[(size_t)(bm + r) * N + bn + cc] = t;
    }
#endif  // KUSE_TC
}

// ---------------------------------------------------------------------------
// Round-to-nearest tf32 prep
// ---------------------------------------------------------------------------
__global__ void round_kernel(const float* __restrict__ in,
                             float* __restrict__ out, size_t n) {
    for (size_t i = (size_t)blockIdx.x * blockDim.x + threadIdx.x; i < n;
         i += (size_t)gridDim.x * blockDim.x)
        out[i] = to_tf32(in[i]);
}

// ---------------------------------------------------------------------------
// Sequential buffer scan; combined is tf32-rounded (GEMM A input).
// 64-thread blocks: 128 blocks spread across SMs (8192 channels total).
// ---------------------------------------------------------------------------
__global__ void scan_kernel(const float* __restrict__ x,
                            const float* __restrict__ decay,
                            float* __restrict__ combined) {
    const int i = blockIdx.x * blockDim.x + threadIdx.x;
    const int b = blockIdx.y;
    const size_t base = (size_t)b * SDIM * IDIM + i;

    float buf = 0.0f;
    for (int t0 = 0; t0 < SDIM; t0 += 8) {
        float d[8], xv[8];
#pragma unroll
        for (int j = 0; j < 8; j++) {
            const size_t idx = base + (size_t)(t0 + j) * IDIM;
            d[j]  = decay[idx];
            xv[j] = x[idx];
        }
#pragma unroll
        for (int j = 0; j < 8; j++) {
            buf = buf * d[j] + (1.0f - d[j]) * xv[j];
            combined[base + (size_t)(t0 + j) * IDIM] = to_tf32(xv[j] * d[j] + buf);
        }
    }
}

// ---------------------------------------------------------------------------
// Launch
// ---------------------------------------------------------------------------
extern "C" void kernel_launch(void* const* d_in, const int* in_sizes, int n_in,
                              void* d_out, int out_size) {
    (void)in_sizes; (void)n_in; (void)out_size;
    const float* x  = (const float*)d_in[0];
    const float* W1 = (const float*)d_in[1];
    const float* b1 = (const float*)d_in[2];
    const float* W2 = (const float*)d_in[3];
    const float* b2 = (const float*)d_in[4];
    const float* Wg = (const float*)d_in[5];
    const float* bg = (const float*)d_in[6];
    float* out = (float*)d_out;

    void *pd, *pc, *ph, *pxr, *pwg, *pw1, *pw2;
    cudaGetSymbolAddress(&pd, g_decay);
    cudaGetSymbolAddress(&pc, g_combined);
    cudaGetSymbolAddress(&ph, g_hidden);
    cudaGetSymbolAddress(&pxr, g_xr);
    cudaGetSymbolAddress(&pwg, g_wgr);
    cudaGetSymbolAddress(&pw1, g_w1r);
    cudaGetSymbolAddress(&pw2, g_w2r);
    float* decay    = (float*)pd;
    float* combined = (float*)pc;
    float* hidden   = (float*)ph;
    float* xr       = (float*)pxr;
    float* wgr      = (float*)pwg;
    float* w1r      = (float*)pw1;
    float* w2r      = (float*)pw2;

    cudaFuncSetAttribute(gemm_tc<EP_SIG, false>,
                         cudaFuncAttributeMaxDynamicSharedMemorySize, SMEM_REQ);
    cudaFuncSetAttribute(gemm_tc<EP_RELU, true>,
                         cudaFuncAttributeMaxDynamicSharedMemorySize, SMEM_REQ);
    cudaFuncSetAttribute(gemm_tc<EP_BIAS, false>,
                         cudaFuncAttributeMaxDynamicSharedMemorySize, SMEM_REQ);

    // tf32 round-to-nearest prep (weights + x)
    round_kernel<<<1024, 256>>>(x, xr, (size_t)MDIM * IDIM);
    round_kernel<<<256, 256>>>(Wg, wgr, (size_t)IDIM * IDIM);
    round_kernel<<<512, 256>>>(W1, w1r, (size_t)HDIM * IDIM);
    round_kernel<<<512, 256>>>(W2, w2r, (size_t)ODIM * HDIM);

    // 1) decay = sigmoid(x @ Wg^T + bg)
    gemm_tc<EP_SIG, false><<<dim3(IDIM / BN, MDIM / BM), 256, SMEM_REQ>>>(
        xr, wgr, decay, bg, MDIM, IDIM, IDIM);
    // 2) recurrence -> combined (tf32-rounded)
    scan_kernel<<<dim3(IDIM / 64, BSZ), 64>>>(x, decay, combined);
    // 3) hidden = relu(combined @ W1^T + b1), tf32-rounded
    gemm_tc<EP_RELU, true><<<dim3(HDIM / BN, MDIM / BM), 256, SMEM_REQ>>>(
        combined, w1r, hidden, b1, MDIM, HDIM, IDIM);
    // 4) out = hidden @ W2^T + b2
    gemm_tc<EP_BIAS, false><<<dim3(ODIM / BN, MDIM / BM), 256, SMEM_REQ>>>(
        hidden, w2r, out, b2, MDIM, ODIM, HDIM);
}